// round 6
// baseline (speedup 1.0000x reference)
#include <cuda_runtime.h>
#include <cuda_fp16.h>
#include <cstdint>

// Problem constants
#define BB 128      // batch
#define TT 256      // timesteps
#define DD 256      // embed dim
#define HH 1024     // hidden
#define CC 10       // classes
#define VV 3        // vocab
#define GRID 128    // persistent CTAs (1 per 8 h-cols)
#define NTHREADS 256
#define NWARP 8
#define KS16 64     // 1024 / 16 (K per m16n8k16 mma)

// SMEM: Bf uint4[2][64][32] = 64KB weight fragments (fp16), then xzsm[3][33]
#define SMEM_BF_BYTES (2 * 64 * 32 * 16)
#define SMEM_XZ_OFF   SMEM_BF_BYTES
#define SMEM_TOTAL    (SMEM_XZ_OFF + 3 * 33 * 4)

// h in A-fragment order, fp16, PAIRED for LDG.128:
// g_hpack[buf][kp][wg][lane] = uint4 { slice(2kp) uint2 , slice(2kp+1) uint2 }
// slice s covers h-cols [8s, 8s+8) (owned by CTA s). For (wg, lane):
//   uint2 = { half2(h[R][c], h[R][c+1]), half2(h[R+8][c], h[R+8][c+1]) },
//   R = 16*wg + lane/4, c = 8*s + 2*(lane%4).
__device__ uint4 g_hpack[2][64][NWARP][32];
__device__ float g_xz3[VV * 4 * HH];   // per-token x-side projection [v][gate*1024+j]
__device__ int   g_xidx[TT * BB];      // token index, time-major
__device__ int   g_x64;
// Per-CTA data-flow flags (R4 scheme). g_flag[ng] = s means CTA ng has
// PUBLISHED h(s-1) (finished step s-2), hence also finished READING h(s-2).
// Consumer of step t needs flag >= t+1 for every producer before consuming
// h(t). WAR safety: writer of h(t+1) (same buffer as h(t-1)) has seen all
// flags >= t+1, which implies every CTA finished reading h(t-1).
__device__ unsigned g_flag[GRID];

// ---------------------------------------------------------------------------
__device__ __forceinline__ unsigned packh2(float a, float b) {
    __half2 h = __floats2half2_rn(a, b);
    return *(unsigned*)&h;
}

__device__ __forceinline__ uint4 ldcg4(const uint4* p) {
    uint4 r;
    asm volatile("ld.global.cg.v4.u32 {%0,%1,%2,%3},[%4];"
                 : "=r"(r.x), "=r"(r.y), "=r"(r.z), "=r"(r.w) : "l"(p));
    return r;
}

__device__ __forceinline__ void mma_f16(float* c, unsigned a0, unsigned a1,
                                        unsigned a2, unsigned a3,
                                        unsigned b0, unsigned b1) {
    asm volatile(
        "mma.sync.aligned.m16n8k16.row.col.f32.f16.f16.f32 "
        "{%0,%1,%2,%3}, {%4,%5,%6,%7}, {%8,%9}, {%0,%1,%2,%3};"
        : "+f"(c[0]), "+f"(c[1]), "+f"(c[2]), "+f"(c[3])
        : "r"(a0), "r"(a1), "r"(a2), "r"(a3), "r"(b0), "r"(b1));
}

__device__ __forceinline__ float tanha(float x) {
    float y;
    asm("tanh.approx.f32 %0,%1;" : "=f"(y) : "f"(x));
    return y;
}

__device__ __forceinline__ float sigmf(float x) {
    float e = __expf(-x);
    float r;
    asm("rcp.approx.f32 %0,%1;" : "=f"(r) : "f"(1.0f + e));
    return r;
}

__device__ __forceinline__ float lstm_elem(float zg, float zi, float zf, float zo, float& c) {
    float gg = tanha(zg);
    float ii = sigmf(zi);
    float ff = sigmf(zf);
    float oo = sigmf(zo);
    c = c * ff + gg * ii;
    return tanha(c) * oo;
}

// Warp-collective single wait for ALL 128 producers: lane L polls flags
// L, L+32, L+64, L+96 with four independent acquire loads (one L2 round
// trip when satisfied), combined via min + ballot.
__device__ __forceinline__ void wait_all(unsigned tgt) {
    const unsigned* f = &g_flag[threadIdx.x & 31];
    unsigned a, b, c, d;
    do {
        asm volatile("ld.acquire.gpu.global.u32 %0,[%1];" : "=r"(a) : "l"(f)      : "memory");
        asm volatile("ld.acquire.gpu.global.u32 %0,[%1];" : "=r"(b) : "l"(f + 32) : "memory");
        asm volatile("ld.acquire.gpu.global.u32 %0,[%1];" : "=r"(c) : "l"(f + 64) : "memory");
        asm volatile("ld.acquire.gpu.global.u32 %0,[%1];" : "=r"(d) : "l"(f + 96) : "memory");
        unsigned m = min(min(a, b), min(c, d));
        if (!__any_sync(0xffffffffu, m < tgt)) break;
    } while (true);
}

__device__ __forceinline__ void publish(int ng, unsigned val) {
    asm volatile("st.release.gpu.global.u32 [%0],%1;"
                 :: "l"(&g_flag[ng]), "r"(val) : "memory");
}

// ---------------------------------------------------------------------------
__global__ void k_init() {
    int tid = threadIdx.x;
    if (tid < GRID) g_flag[tid] = 0u;
}

// Detect x dtype without reading past an int32-sized allocation.
__global__ void k_detect(const unsigned* __restrict__ xw) {
    __shared__ int flag;
    if (threadIdx.x == 0) flag = 0;
    __syncthreads();
    for (int i = threadIdx.x; i < 2048; i += blockDim.x)
        if (xw[2 * i + 1] != 0u) flag = 1;
    __syncthreads();
    if (threadIdx.x == 0) g_x64 = (flag == 0) ? 1 : 0;
}

__global__ void k_idx(const void* __restrict__ x) {
    int b = blockIdx.x;
    int t = threadIdx.x;
    long long v;
    if (g_x64) v = ((const long long*)x)[(size_t)b * TT + t];
    else       v = ((const int*)x)[(size_t)b * TT + t];
    g_xidx[t * BB + b] = (int)v;
}

__global__ void k_xz3(const float* __restrict__ emb,
                      const float* __restrict__ W_gx, const float* __restrict__ W_ix,
                      const float* __restrict__ W_fx, const float* __restrict__ W_ox,
                      const float* __restrict__ b_g, const float* __restrict__ b_i,
                      const float* __restrict__ b_f, const float* __restrict__ b_o) {
    int gid = blockIdx.x * blockDim.x + threadIdx.x;
    if (gid >= VV * 4 * HH) return;
    int v = gid >> 12;
    int col = gid & 4095;
    int gate = col >> 10;
    int j = col & 1023;
    const float* W = (gate == 0) ? W_gx : (gate == 1) ? W_ix : (gate == 2) ? W_fx : W_ox;
    const float* bb = (gate == 0) ? b_g : (gate == 1) ? b_i : (gate == 2) ? b_f : b_o;
    float s = bb[j];
    const float* ev = emb + v * DD;
#pragma unroll 8
    for (int d = 0; d < DD; ++d) s += ev[d] * W[d * HH + j];
    g_xz3[gid] = s;
}

// ---------------------------------------------------------------------------
// Persistent recurrent kernel. CTA ng owns h-cols [8ng, 8ng+8).
// Warp wg: batch rows [16wg, 16wg+16), all 32 z-cols (ntile = gate).
// c-state in registers; z never leaves the mma accumulators.
// Per-step: ONE flag wait, 64 LDG.128 streamed at full MLP, block publish.
__global__ void __launch_bounds__(NTHREADS, 1)
lstm_persistent(const float* __restrict__ W_gh, const float* __restrict__ W_ih,
                const float* __restrict__ W_fh, const float* __restrict__ W_oh) {
    extern __shared__ __align__(16) char smem[];
    uint4* Bf = (uint4*)smem;                     // [2][64][32]
    float* xzsm = (float*)(smem + SMEM_XZ_OFF);   // [3][33]

    const int ng = blockIdx.x;
    const int tid = threadIdx.x;
    const int wg = tid >> 5;
    const int lane = tid & 31;
    const int q = lane & 3;
    const int r4 = lane >> 2;
    const int R = 16 * wg + r4;

    // ---- One-time: weight slice -> fp16 B-fragments in SMEM ----
    for (int i = tid; i < 2 * KS16 * 32; i += NTHREADS) {
        int t = i & 31;
        int ks = (i >> 5) & 63;
        int p = i >> 11;                      // 0: gates g,i  1: gates f,o
        int col = ng * 8 + (t >> 2);
        int k0 = 16 * ks + 2 * (t & 3);
        const float* WA = p ? W_fh : W_gh;
        const float* WB = p ? W_oh : W_ih;
        uint4 v;
        v.x = packh2(WA[(size_t)k0 * HH + col],       WA[(size_t)(k0 + 1) * HH + col]);
        v.y = packh2(WA[(size_t)(k0 + 8) * HH + col], WA[(size_t)(k0 + 9) * HH + col]);
        v.z = packh2(WB[(size_t)k0 * HH + col],       WB[(size_t)(k0 + 1) * HH + col]);
        v.w = packh2(WB[(size_t)(k0 + 8) * HH + col], WB[(size_t)(k0 + 9) * HH + col]);
        Bf[i] = v;
    }

    // xz slice: xzsm[v][gate*8 + j] for this CTA's 8 cols
    for (int i = tid; i < VV * 32; i += NTHREADS) {
        int v = i >> 5;
        int lc = i & 31;
        xzsm[v * 33 + lc] = g_xz3[v * 4096 + (lc >> 3) * HH + ng * 8 + (lc & 7)];
    }

    // Producer write slot for this (ng, wg, lane): 8-byte half of a uint4.
    const int kp = ng >> 1;
    const int half = ng & 1;
    uint2* slot0 = (uint2*)((char*)&g_hpack[0][kp][wg][lane] + half * 8);
    uint2* slot1 = (uint2*)((char*)&g_hpack[1][kp][wg][lane] + half * 8);

    // h(0) = 0 for our fragment
    {
        uint2 z; z.x = 0u; z.y = 0u;
        *slot0 = z;
    }
    __syncthreads();
    if (tid == 0) publish(ng, 1u);

    float c0 = 0.0f, c1 = 0.0f, c2 = 0.0f, c3 = 0.0f;

    for (int t = 0; t < TT; ++t) {
        const uint4* hp = &g_hpack[t & 1][0][wg][lane];   // stride per kp = 256 uint4
        const uint4* bf0 = Bf + lane;
        const uint4* bf1 = Bf + 2048 + lane;

        // Prefetch token indices for this step
        int vA = __ldg(&g_xidx[t * BB + R]);
        int vB = __ldg(&g_xidx[t * BB + R + 8]);

        float acc[4][4];
#pragma unroll
        for (int g = 0; g < 4; ++g)
#pragma unroll
            for (int e = 0; e < 4; ++e) acc[g][e] = 0.0f;

        // Single wait for all 128 producers, then one straight-line
        // 64-chunk loop: ptxas pipelines LDG.128 at full MLP.
        wait_all((unsigned)(t + 1));

#pragma unroll 16
        for (int ks = 0; ks < KS16; ++ks) {
            uint4 A = ldcg4(hp + ks * 256);   // A01 = .x/.y, A23 = .z/.w
            uint4 B01 = bf0[ks * 32];
            uint4 B23 = bf1[ks * 32];
            mma_f16(acc[0], A.x, A.y, A.z, A.w, B01.x, B01.y);
            mma_f16(acc[1], A.x, A.y, A.z, A.w, B01.z, B01.w);
            mma_f16(acc[2], A.x, A.y, A.z, A.w, B23.x, B23.y);
            mma_f16(acc[3], A.x, A.y, A.z, A.w, B23.z, B23.w);
        }

        // Gate math entirely in registers (C-fragment == gate-math element set)
        const float* xA = xzsm + vA * 33 + 2 * q;
        const float* xB = xzsm + vB * 33 + 2 * q;

        float h0 = lstm_elem(acc[0][0] + xA[0], acc[1][0] + xA[8],
                             acc[2][0] + xA[16], acc[3][0] + xA[24], c0);
        float h1 = lstm_elem(acc[0][1] + xA[1], acc[1][1] + xA[9],
                             acc[2][1] + xA[17], acc[3][1] + xA[25], c1);
        float h2 = lstm_elem(acc[0][2] + xB[0], acc[1][2] + xB[8],
                             acc[2][2] + xB[16], acc[3][2] + xB[24], c2);
        float h3 = lstm_elem(acc[0][3] + xB[1], acc[1][3] + xB[9],
                             acc[2][3] + xB[17], acc[3][3] + xB[25], c3);

        uint2 out;
        out.x = packh2(h0, h1);
        out.y = packh2(h2, h3);
        *((t & 1) ? slot0 : slot1) = out;     // h(t+1) -> buffer (t+1)&1

        // Publish h(t+1): all CTA stores ordered before the release store.
        __syncthreads();
        if (tid == 0) publish(ng, (unsigned)(t + 2));
    }
}

// ---------------------------------------------------------------------------
// Final projection + log_softmax; decodes packed fragment layout (buf 0).
__global__ void k_final(const float* __restrict__ W_ph, const float* __restrict__ b_p,
                        float* __restrict__ out) {
    __shared__ float part[CC][128];
    __shared__ float lg[CC];
    __shared__ float red[2];
    int b = blockIdx.x;
    int tid = threadIdx.x;
    int wg = b >> 4;
    int rr = b & 7;
    int e1 = (b >> 3) & 1;

    float loc[CC];
#pragma unroll
    for (int c = 0; c < CC; ++c) loc[c] = 0.0f;
    for (int col = tid; col < HH; col += 128) {
        int ns2 = col >> 3;        // 8-col slice
        int kp = ns2 >> 1;
        int half = ns2 & 1;
        int q = (col & 7) >> 1;
        int e0 = col & 1;
        uint4 ent = g_hpack[0][kp][wg][rr * 4 + q];
        unsigned word;
        if (half) word = e1 ? ent.w : ent.z;
        else      word = e1 ? ent.y : ent.x;
        __half2 hh = *(__half2*)&word;
        float hv = e0 ? __high2float(hh) : __low2float(hh);
#pragma unroll
        for (int c = 0; c < CC; ++c) loc[c] += hv * W_ph[col * CC + c];
    }
#pragma unroll
    for (int c = 0; c < CC; ++c) part[c][tid] = loc[c];
    __syncthreads();
    if (tid < CC) {
        float s = 0.0f;
        for (int k = 0; k < 128; ++k) s += part[tid][k];
        lg[tid] = s + b_p[tid];
    }
    __syncthreads();
    if (tid == 0) {
        float m = -1e30f;
        for (int c = 0; c < CC; ++c) m = fmaxf(m, lg[c]);
        float s = 0.0f;
        for (int c = 0; c < CC; ++c) s += expf(lg[c] - m);
        red[0] = m;
        red[1] = logf(s);
    }
    __syncthreads();
    if (tid < CC) out[b * CC + tid] = lg[tid] - red[0] - red[1];
}

// ---------------------------------------------------------------------------
extern "C" void kernel_launch(void* const* d_in, const int* in_sizes, int n_in,
                              void* d_out, int out_size) {
    const void* x        = d_in[0];
    const float* emb     = (const float*)d_in[1];
    const float* W_gx    = (const float*)d_in[2];
    const float* W_ix    = (const float*)d_in[3];
    const float* W_fx    = (const float*)d_in[4];
    const float* W_ox    = (const float*)d_in[5];
    const float* W_gh    = (const float*)d_in[6];
    const float* W_ih    = (const float*)d_in[7];
    const float* W_fh    = (const float*)d_in[8];
    const float* W_oh    = (const float*)d_in[9];
    const float* b_g     = (const float*)d_in[10];
    const float* b_i     = (const float*)d_in[11];
    const float* b_f     = (const float*)d_in[12];
    const float* b_o     = (const float*)d_in[13];
    const float* W_ph    = (const float*)d_in[14];
    const float* b_p     = (const float*)d_in[15];
    float* out = (float*)d_out;

    cudaFuncSetAttribute(lstm_persistent, cudaFuncAttributeMaxDynamicSharedMemorySize,
                         SMEM_TOTAL);

    k_init<<<1, 128>>>();
    k_detect<<<1, 256>>>((const unsigned*)x);
    k_idx<<<BB, TT>>>(x);
    k_xz3<<<(VV * 4 * HH + 255) / 256, 256>>>(emb, W_gx, W_ix, W_fx, W_ox, b_g, b_i, b_f, b_o);
    lstm_persistent<<<GRID, NTHREADS, SMEM_TOTAL>>>(W_gh, W_ih, W_fh, W_oh);
    k_final<<<BB, 128>>>(W_ph, b_p, out);
}

// round 7
// speedup vs baseline: 1.1997x; 1.1997x over previous
#include <cuda_runtime.h>
#include <cuda_fp16.h>
#include <cstdint>

// Problem constants
#define BB 128      // batch
#define TT 256      // timesteps
#define DD 256      // embed dim
#define HH 1024     // hidden
#define CC 10       // classes
#define VV 3        // vocab
#define GRID 128    // persistent CTAs (1 per 8 h-cols)
#define NTHREADS 128
#define KS16 64     // 1024 / 16 (K per m16n8k16 mma)

// SMEM: Bf uint4[2][64][32] = 64KB weight fragments (fp16), then xzsm[3][33]
#define SMEM_BF_BYTES (2 * 64 * 32 * 16)
#define SMEM_XZ_OFF   SMEM_BF_BYTES
#define SMEM_TOTAL    (SMEM_XZ_OFF + 3 * 33 * 4)

// h in A-fragment order, fp16 (R2-R4 proven layout):
// g_hfrag[buf][s][rg][lane], lane=(r4=lane/4, q=lane%4):
//   .x = half2(h[16rg+r4][8s+2q],   h[16rg+r4][8s+2q+1])
//   .y = half2(h[16rg+8+r4][8s+2q], h[16rg+8+r4][8s+2q+1])
// slice s = h-cols [8s, 8s+8), owned by CTA s.
__device__ uint2 g_hfrag[2][128][8][32];
__device__ float g_xz3[VV * 4 * HH];   // per-token x-side projection [v][gate*1024+j]
__device__ int   g_xidx[TT * BB];      // token index, time-major
__device__ int   g_x64;
// Per-CTA data-flow flags (R4 scheme). g_flag[ng] = s means CTA ng has
// PUBLISHED h(s-1) (finished step s-2), hence also finished READING h(s-2).
// Consumer of step t needs flag >= t+1 for a producer before consuming its
// h(t) slice. WAR safety: writer of h(t+1) (same buffer as h(t-1)) has seen
// all flags >= t+1, which implies every CTA finished reading h(t-1).
__device__ unsigned g_flag[GRID];

// ---------------------------------------------------------------------------
__device__ __forceinline__ unsigned packh2(float a, float b) {
    __half2 h = __floats2half2_rn(a, b);
    return *(unsigned*)&h;
}

__device__ __forceinline__ uint2 ldcg2(const uint2* p) {
    uint2 r;
    asm volatile("ld.global.cg.v2.u32 {%0,%1},[%2];" : "=r"(r.x), "=r"(r.y) : "l"(p));
    return r;
}

__device__ __forceinline__ void mma_f16(float* c, unsigned a0, unsigned a1,
                                        unsigned a2, unsigned a3,
                                        unsigned b0, unsigned b1) {
    asm volatile(
        "mma.sync.aligned.m16n8k16.row.col.f32.f16.f16.f32 "
        "{%0,%1,%2,%3}, {%4,%5,%6,%7}, {%8,%9}, {%0,%1,%2,%3};"
        : "+f"(c[0]), "+f"(c[1]), "+f"(c[2]), "+f"(c[3])
        : "r"(a0), "r"(a1), "r"(a2), "r"(a3), "r"(b0), "r"(b1));
}

__device__ __forceinline__ float tanha(float x) {
    float y;
    asm("tanh.approx.f32 %0,%1;" : "=f"(y) : "f"(x));
    return y;
}

__device__ __forceinline__ float sigmf(float x) {
    float e = __expf(-x);
    float r;
    asm("rcp.approx.f32 %0,%1;" : "=f"(r) : "f"(1.0f + e));
    return r;
}

__device__ __forceinline__ float lstm_elem(float zg, float zi, float zf, float zo, float& c) {
    float gg = tanha(zg);
    float ii = sigmf(zi);
    float ff = sigmf(zf);
    float oo = sigmf(zo);
    c = c * ff + gg * ii;
    return tanha(c) * oo;
}

// Warp-collective: wait until producers [32g, 32g+32) have flag >= tgt.
__device__ __forceinline__ void wait_group(int g, unsigned tgt) {
    const unsigned* f = &g_flag[g * 32 + (threadIdx.x & 31)];
    unsigned v;
    do {
        asm volatile("ld.acquire.gpu.global.u32 %0,[%1];" : "=r"(v) : "l"(f) : "memory");
    } while (__any_sync(0xffffffffu, v < tgt));
}

__device__ __forceinline__ void publish(int ng, unsigned val) {
    asm volatile("st.release.gpu.global.u32 [%0],%1;"
                 :: "l"(&g_flag[ng]), "r"(val) : "memory");
}

// ---------------------------------------------------------------------------
__global__ void k_init() {
    int tid = threadIdx.x;
    if (tid < GRID) g_flag[tid] = 0u;
}

// Detect x dtype without reading past an int32-sized allocation.
__global__ void k_detect(const unsigned* __restrict__ xw) {
    __shared__ int flag;
    if (threadIdx.x == 0) flag = 0;
    __syncthreads();
    for (int i = threadIdx.x; i < 2048; i += blockDim.x)
        if (xw[2 * i + 1] != 0u) flag = 1;
    __syncthreads();
    if (threadIdx.x == 0) g_x64 = (flag == 0) ? 1 : 0;
}

__global__ void k_idx(const void* __restrict__ x) {
    int b = blockIdx.x;
    int t = threadIdx.x;
    long long v;
    if (g_x64) v = ((const long long*)x)[(size_t)b * TT + t];
    else       v = ((const int*)x)[(size_t)b * TT + t];
    g_xidx[t * BB + b] = (int)v;
}

__global__ void k_xz3(const float* __restrict__ emb,
                      const float* __restrict__ W_gx, const float* __restrict__ W_ix,
                      const float* __restrict__ W_fx, const float* __restrict__ W_ox,
                      const float* __restrict__ b_g, const float* __restrict__ b_i,
                      const float* __restrict__ b_f, const float* __restrict__ b_o) {
    int gid = blockIdx.x * blockDim.x + threadIdx.x;
    if (gid >= VV * 4 * HH) return;
    int v = gid >> 12;
    int col = gid & 4095;
    int gate = col >> 10;
    int j = col & 1023;
    const float* W = (gate == 0) ? W_gx : (gate == 1) ? W_ix : (gate == 2) ? W_fx : W_ox;
    const float* bb = (gate == 0) ? b_g : (gate == 1) ? b_i : (gate == 2) ? b_f : b_o;
    float s = bb[j];
    const float* ev = emb + v * DD;
#pragma unroll 8
    for (int d = 0; d < DD; ++d) s += ev[d] * W[d * HH + j];
    g_xz3[gid] = s;
}

// ---------------------------------------------------------------------------
// Persistent recurrent kernel. CTA ng owns h-cols [8ng, 8ng+8) (32 z-cols).
// 4 warps, warp wg: batch rows [32wg, 32wg+32) = 2 m-tiles; each B fragment
// is read from SMEM once and used by both m-tiles (halves LDS traffic vs R4).
// c-state in registers; z never leaves the mma accumulators.
__global__ void __launch_bounds__(NTHREADS, 1)
lstm_persistent(const float* __restrict__ W_gh, const float* __restrict__ W_ih,
                const float* __restrict__ W_fh, const float* __restrict__ W_oh) {
    extern __shared__ __align__(16) char smem[];
    uint4* Bf = (uint4*)smem;                     // [2][64][32]
    float* xzsm = (float*)(smem + SMEM_XZ_OFF);   // [3][33]

    const int ng = blockIdx.x;
    const int tid = threadIdx.x;
    const int wg = tid >> 5;       // 0..3
    const int lane = tid & 31;
    const int q = lane & 3;
    const int r4 = lane >> 2;
    const int R0 = 32 * wg + r4;   // rows R0, R0+8 (mt0), R0+16, R0+24 (mt1)

    // ---- One-time: weight slice -> fp16 B-fragments in SMEM ----
    for (int i = tid; i < 2 * KS16 * 32; i += NTHREADS) {
        int t = i & 31;
        int ks = (i >> 5) & 63;
        int p = i >> 11;                      // 0: gates g,i  1: gates f,o
        int col = ng * 8 + (t >> 2);
        int k0 = 16 * ks + 2 * (t & 3);
        const float* WA = p ? W_fh : W_gh;
        const float* WB = p ? W_oh : W_ih;
        uint4 v;
        v.x = packh2(WA[(size_t)k0 * HH + col],       WA[(size_t)(k0 + 1) * HH + col]);
        v.y = packh2(WA[(size_t)(k0 + 8) * HH + col], WA[(size_t)(k0 + 9) * HH + col]);
        v.z = packh2(WB[(size_t)k0 * HH + col],       WB[(size_t)(k0 + 1) * HH + col]);
        v.w = packh2(WB[(size_t)(k0 + 8) * HH + col], WB[(size_t)(k0 + 9) * HH + col]);
        Bf[i] = v;
    }

    // xz slice: xzsm[v][gate*8 + j] for this CTA's 8 cols
    for (int i = tid; i < VV * 32; i += NTHREADS) {
        int v = i >> 5;
        int lc = i & 31;
        xzsm[v * 33 + lc] = g_xz3[v * 4096 + (lc >> 3) * HH + ng * 8 + (lc & 7)];
    }

    // h(0) = 0 for our fragments (this thread produces row-groups 2wg, 2wg+1)
    {
        uint2 z; z.x = 0u; z.y = 0u;
        g_hfrag[0][ng][2 * wg][lane] = z;
        g_hfrag[0][ng][2 * wg + 1][lane] = z;
    }
    __syncthreads();
    if (tid == 0) publish(ng, 1u);

    // c-state: [mt][elem] with elem: 0=(rowA,2q) 1=(rowA,2q+1) 2=(rowB,2q) 3=(rowB,2q+1)
    float cst[2][4];
#pragma unroll
    for (int m = 0; m < 2; ++m)
#pragma unroll
        for (int e = 0; e < 4; ++e) cst[m][e] = 0.0f;

    for (int t = 0; t < TT; ++t) {
        const uint2* hb0 = &g_hfrag[t & 1][0][2 * wg][lane];       // mt0, slice stride 256
        const uint2* hb1 = &g_hfrag[t & 1][0][2 * wg + 1][lane];   // mt1
        const uint4* bf0 = Bf + lane;
        const uint4* bf1 = Bf + 2048 + lane;

        // Prefetch the 4 token indices for this thread's rows
        int v0 = __ldg(&g_xidx[t * BB + R0]);
        int v1 = __ldg(&g_xidx[t * BB + R0 + 8]);
        int v2 = __ldg(&g_xidx[t * BB + R0 + 16]);
        int v3 = __ldg(&g_xidx[t * BB + R0 + 24]);

        float acc[2][4][4];
#pragma unroll
        for (int m = 0; m < 2; ++m)
#pragma unroll
            for (int g = 0; g < 4; ++g)
#pragma unroll
                for (int e = 0; e < 4; ++e) acc[m][g][e] = 0.0f;

        // 4 grouped waits in k-order (R4-proven): group g covers producers
        // [32g,32g+32) = k-steps [16g,16g+16). Pipelines producer skew.
#pragma unroll 1
        for (int grp = 0; grp < 4; ++grp) {
            wait_group(grp, (unsigned)(t + 1));
#pragma unroll 8
            for (int ks = 16 * grp; ks < 16 * grp + 16; ++ks) {
                uint2 A001 = ldcg2(hb0 + (2 * ks) * 256);
                uint2 A023 = ldcg2(hb0 + (2 * ks + 1) * 256);
                uint2 A101 = ldcg2(hb1 + (2 * ks) * 256);
                uint2 A123 = ldcg2(hb1 + (2 * ks + 1) * 256);
                uint4 B01 = bf0[ks * 32];
                uint4 B23 = bf1[ks * 32];
                // B fragment reused for both m-tiles
                mma_f16(acc[0][0], A001.x, A001.y, A023.x, A023.y, B01.x, B01.y);
                mma_f16(acc[1][0], A101.x, A101.y, A123.x, A123.y, B01.x, B01.y);
                mma_f16(acc[0][1], A001.x, A001.y, A023.x, A023.y, B01.z, B01.w);
                mma_f16(acc[1][1], A101.x, A101.y, A123.x, A123.y, B01.z, B01.w);
                mma_f16(acc[0][2], A001.x, A001.y, A023.x, A023.y, B23.x, B23.y);
                mma_f16(acc[1][2], A101.x, A101.y, A123.x, A123.y, B23.x, B23.y);
                mma_f16(acc[0][3], A001.x, A001.y, A023.x, A023.y, B23.z, B23.w);
                mma_f16(acc[1][3], A101.x, A101.y, A123.x, A123.y, B23.z, B23.w);
            }
        }

        // Gate math in registers (C-fragment == gate-math element set)
        const float* x0 = xzsm + v0 * 33 + 2 * q;
        const float* x1 = xzsm + v1 * 33 + 2 * q;
        const float* x2 = xzsm + v2 * 33 + 2 * q;
        const float* x3 = xzsm + v3 * 33 + 2 * q;

        float h00 = lstm_elem(acc[0][0][0] + x0[0], acc[0][1][0] + x0[8],
                              acc[0][2][0] + x0[16], acc[0][3][0] + x0[24], cst[0][0]);
        float h01 = lstm_elem(acc[0][0][1] + x0[1], acc[0][1][1] + x0[9],
                              acc[0][2][1] + x0[17], acc[0][3][1] + x0[25], cst[0][1]);
        float h02 = lstm_elem(acc[0][0][2] + x1[0], acc[0][1][2] + x1[8],
                              acc[0][2][2] + x1[16], acc[0][3][2] + x1[24], cst[0][2]);
        float h03 = lstm_elem(acc[0][0][3] + x1[1], acc[0][1][3] + x1[9],
                              acc[0][2][3] + x1[17], acc[0][3][3] + x1[25], cst[0][3]);

        float h10 = lstm_elem(acc[1][0][0] + x2[0], acc[1][1][0] + x2[8],
                              acc[1][2][0] + x2[16], acc[1][3][0] + x2[24], cst[1][0]);
        float h11 = lstm_elem(acc[1][0][1] + x2[1], acc[1][1][1] + x2[9],
                              acc[1][2][1] + x2[17], acc[1][3][1] + x2[25], cst[1][1]);
        float h12 = lstm_elem(acc[1][0][2] + x3[0], acc[1][1][2] + x3[8],
                              acc[1][2][2] + x3[16], acc[1][3][2] + x3[24], cst[1][2]);
        float h13 = lstm_elem(acc[1][0][3] + x3[1], acc[1][1][3] + x3[9],
                              acc[1][2][3] + x3[17], acc[1][3][3] + x3[25], cst[1][3]);

        uint2 out0, out1;
        out0.x = packh2(h00, h01);   // (R0,   2q / 2q+1)
        out0.y = packh2(h02, h03);   // (R0+8, 2q / 2q+1)
        out1.x = packh2(h10, h11);   // (R0+16, ...)
        out1.y = packh2(h12, h13);   // (R0+24, ...)
        g_hfrag[(t + 1) & 1][ng][2 * wg][lane] = out0;
        g_hfrag[(t + 1) & 1][ng][2 * wg + 1][lane] = out1;

        // Publish h(t+1): all CTA stores ordered before the release store.
        __syncthreads();
        if (tid == 0) publish(ng, (unsigned)(t + 2));
    }
}

// ---------------------------------------------------------------------------
// Final projection + log_softmax; decodes fragment layout. h_final in buf 0.
__global__ void k_final(const float* __restrict__ W_ph, const float* __restrict__ b_p,
                        float* __restrict__ out) {
    __shared__ float part[CC][128];
    __shared__ float lg[CC];
    __shared__ float red[2];
    int b = blockIdx.x;
    int tid = threadIdx.x;
    int wg = b >> 4;           // row group of 16
    int rr = b & 7;
    int e1 = (b >> 3) & 1;     // 0: row = 16wg+rr, 1: row = 16wg+8+rr

    float loc[CC];
#pragma unroll
    for (int c = 0; c < CC; ++c) loc[c] = 0.0f;
    for (int col = tid; col < HH; col += 128) {
        int ns2 = col >> 3;
        int q = (col & 7) >> 1;
        int e0 = col & 1;
        uint2 ent = g_hfrag[0][ns2][wg][rr * 4 + q];
        unsigned word = e1 ? ent.y : ent.x;
        __half2 hh = *(__half2*)&word;
        float hv = e0 ? __high2float(hh) : __low2float(hh);
#pragma unroll
        for (int c = 0; c < CC; ++c) loc[c] += hv * W_ph[col * CC + c];
    }
#pragma unroll
    for (int c = 0; c < CC; ++c) part[c][tid] = loc[c];
    __syncthreads();
    if (tid < CC) {
        float s = 0.0f;
        for (int k = 0; k < 128; ++k) s += part[tid][k];
        lg[tid] = s + b_p[tid];
    }
    __syncthreads();
    if (tid == 0) {
        float m = -1e30f;
        for (int c = 0; c < CC; ++c) m = fmaxf(m, lg[c]);
        float s = 0.0f;
        for (int c = 0; c < CC; ++c) s += expf(lg[c] - m);
        red[0] = m;
        red[1] = logf(s);
    }
    __syncthreads();
    if (tid < CC) out[b * CC + tid] = lg[tid] - red[0] - red[1];
}

// ---------------------------------------------------------------------------
extern "C" void kernel_launch(void* const* d_in, const int* in_sizes, int n_in,
                              void* d_out, int out_size) {
    const void* x        = d_in[0];
    const float* emb     = (const float*)d_in[1];
    const float* W_gx    = (const float*)d_in[2];
    const float* W_ix    = (const float*)d_in[3];
    const float* W_fx    = (const float*)d_in[4];
    const float* W_ox    = (const float*)d_in[5];
    const float* W_gh    = (const float*)d_in[6];
    const float* W_ih    = (const float*)d_in[7];
    const float* W_fh    = (const float*)d_in[8];
    const float* W_oh    = (const float*)d_in[9];
    const float* b_g     = (const float*)d_in[10];
    const float* b_i     = (const float*)d_in[11];
    const float* b_f     = (const float*)d_in[12];
    const float* b_o     = (const float*)d_in[13];
    const float* W_ph    = (const float*)d_in[14];
    const float* b_p     = (const float*)d_in[15];
    float* out = (float*)d_out;

    cudaFuncSetAttribute(lstm_persistent, cudaFuncAttributeMaxDynamicSharedMemorySize,
                         SMEM_TOTAL);

    k_init<<<1, 128>>>();
    k_detect<<<1, 256>>>((const unsigned*)x);
    k_idx<<<BB, TT>>>(x);
    k_xz3<<<(VV * 4 * HH + 255) / 256, 256>>>(emb, W_gx, W_ix, W_fx, W_ox, b_g, b_i, b_f, b_o);
    lstm_persistent<<<GRID, NTHREADS, SMEM_TOTAL>>>(W_gh, W_ih, W_fh, W_oh);
    k_final<<<BB, 128>>>(W_ph, b_p, out);
}

// round 8
// speedup vs baseline: 1.2701x; 1.0587x over previous
#include <cuda_runtime.h>
#include <cuda_fp16.h>
#include <cstdint>

// Problem constants
#define BB 128      // batch
#define TT 256      // timesteps
#define DD 256      // embed dim
#define HH 1024     // hidden
#define CC 10       // classes
#define VV 3        // vocab
#define GRID 128    // persistent CTAs (1 per 8 h-cols)
#define NTHREADS 256
#define NWARP 8
#define KS16 64     // 1024 / 16 (K per m16n8k16 mma)

// SMEM: Bf uint4[2][64][32] = 64KB weight fragments (fp16), then xzsm[3][33]
#define SMEM_BF_BYTES (2 * 64 * 32 * 16)
#define SMEM_XZ_OFF   SMEM_BF_BYTES
#define SMEM_TOTAL    (SMEM_XZ_OFF + 3 * 33 * 4)

// h in A-fragment order, fp16, PAIRED for LDG.128:
// g_hpack[buf][kp][wg][lane] = uint4 { slice(2kp) uint2 , slice(2kp+1) uint2 }
// slice s covers h-cols [8s, 8s+8) (owned by CTA s). For (wg, lane):
//   uint2 = { half2(h[R][c], h[R][c+1]), half2(h[R+8][c], h[R+8][c+1]) },
//   R = 16*wg + lane/4, c = 8*s + 2*(lane%4).
__device__ uint4 g_hpack[2][64][NWARP][32];
__device__ float g_xz3[VV * 4 * HH];   // per-token x-side projection [v][gate*1024+j]
__device__ int   g_xidx[TT * BB];      // token index, time-major
__device__ int   g_x64;
// Arrival-counting data-flow flags. Each of CTA ng's 8 warps adds 1 to
// g_flag[ng] (release) after storing its h(s) fragment. flag == 8*(s+1)
// means ALL of CTA ng's h(s) fragments are published, and every warp has
// finished reading h(s-1). Consumer of h(t) waits flag >= 8*(t+1).
// WAR safety: a warp writes h(t+2) (buffer t&1, = h(t)'s buffer) only after
// passing all group waits at level 8*(t+2), i.e. after every warp of every
// CTA stored h(t+1) and therefore finished reading h(t).
__device__ unsigned g_flag[GRID];

// ---------------------------------------------------------------------------
__device__ __forceinline__ unsigned packh2(float a, float b) {
    __half2 h = __floats2half2_rn(a, b);
    return *(unsigned*)&h;
}

__device__ __forceinline__ uint4 ldcg4(const uint4* p) {
    uint4 r;
    asm volatile("ld.global.cg.v4.u32 {%0,%1,%2,%3},[%4];"
                 : "=r"(r.x), "=r"(r.y), "=r"(r.z), "=r"(r.w) : "l"(p));
    return r;
}

__device__ __forceinline__ void mma_f16(float* c, unsigned a0, unsigned a1,
                                        unsigned a2, unsigned a3,
                                        unsigned b0, unsigned b1) {
    asm volatile(
        "mma.sync.aligned.m16n8k16.row.col.f32.f16.f16.f32 "
        "{%0,%1,%2,%3}, {%4,%5,%6,%7}, {%8,%9}, {%0,%1,%2,%3};"
        : "+f"(c[0]), "+f"(c[1]), "+f"(c[2]), "+f"(c[3])
        : "r"(a0), "r"(a1), "r"(a2), "r"(a3), "r"(b0), "r"(b1));
}

__device__ __forceinline__ float tanha(float x) {
    float y;
    asm("tanh.approx.f32 %0,%1;" : "=f"(y) : "f"(x));
    return y;
}

__device__ __forceinline__ float sigmf(float x) {
    float e = __expf(-x);
    float r;
    asm("rcp.approx.f32 %0,%1;" : "=f"(r) : "f"(1.0f + e));
    return r;
}

__device__ __forceinline__ float lstm_elem(float zg, float zi, float zf, float zo, float& c) {
    float gg = tanha(zg);
    float ii = sigmf(zi);
    float ff = sigmf(zf);
    float oo = sigmf(zo);
    c = c * ff + gg * ii;
    return tanha(c) * oo;
}

// Warp-collective: wait until producers [32g, 32g+32) have flag >= tgt.
__device__ __forceinline__ void wait_group(int g, unsigned tgt) {
    const unsigned* f = &g_flag[g * 32 + (threadIdx.x & 31)];
    unsigned v;
    do {
        asm volatile("ld.acquire.gpu.global.u32 %0,[%1];" : "=r"(v) : "l"(f) : "memory");
    } while (__any_sync(0xffffffffu, v < tgt));
}

// Warp publishes its fragment: syncwarp orders the warp's stores before
// lane 0's cumulative release-reduction on the CTA flag.
__device__ __forceinline__ void publish_warp(int ng, int lane) {
    __syncwarp();
    if (lane == 0)
        asm volatile("red.release.gpu.global.add.u32 [%0],%1;"
                     :: "l"(&g_flag[ng]), "r"(1u) : "memory");
}

// ---------------------------------------------------------------------------
__global__ void k_init() {
    int tid = threadIdx.x;
    if (tid < GRID) g_flag[tid] = 0u;
}

// Detect x dtype without reading past an int32-sized allocation.
__global__ void k_detect(const unsigned* __restrict__ xw) {
    __shared__ int flag;
    if (threadIdx.x == 0) flag = 0;
    __syncthreads();
    for (int i = threadIdx.x; i < 2048; i += blockDim.x)
        if (xw[2 * i + 1] != 0u) flag = 1;
    __syncthreads();
    if (threadIdx.x == 0) g_x64 = (flag == 0) ? 1 : 0;
}

__global__ void k_idx(const void* __restrict__ x) {
    int b = blockIdx.x;
    int t = threadIdx.x;
    long long v;
    if (g_x64) v = ((const long long*)x)[(size_t)b * TT + t];
    else       v = ((const int*)x)[(size_t)b * TT + t];
    g_xidx[t * BB + b] = (int)v;
}

__global__ void k_xz3(const float* __restrict__ emb,
                      const float* __restrict__ W_gx, const float* __restrict__ W_ix,
                      const float* __restrict__ W_fx, const float* __restrict__ W_ox,
                      const float* __restrict__ b_g, const float* __restrict__ b_i,
                      const float* __restrict__ b_f, const float* __restrict__ b_o) {
    int gid = blockIdx.x * blockDim.x + threadIdx.x;
    if (gid >= VV * 4 * HH) return;
    int v = gid >> 12;
    int col = gid & 4095;
    int gate = col >> 10;
    int j = col & 1023;
    const float* W = (gate == 0) ? W_gx : (gate == 1) ? W_ix : (gate == 2) ? W_fx : W_ox;
    const float* bb = (gate == 0) ? b_g : (gate == 1) ? b_i : (gate == 2) ? b_f : b_o;
    float s = bb[j];
    const float* ev = emb + v * DD;
#pragma unroll 8
    for (int d = 0; d < DD; ++d) s += ev[d] * W[d * HH + j];
    g_xz3[gid] = s;
}

// ---------------------------------------------------------------------------
// Persistent recurrent kernel (R4 shape). CTA ng owns h-cols [8ng, 8ng+8).
// Warp wg: batch rows [16wg, 16wg+16), all 32 z-cols (ntile = gate).
// c-state in registers; z never leaves the mma accumulators.
// R8 deltas vs R4: LDG.128-paired h reads; per-warp arrival publish.
__global__ void __launch_bounds__(NTHREADS, 1)
lstm_persistent(const float* __restrict__ W_gh, const float* __restrict__ W_ih,
                const float* __restrict__ W_fh, const float* __restrict__ W_oh) {
    extern __shared__ __align__(16) char smem[];
    uint4* Bf = (uint4*)smem;                     // [2][64][32]
    float* xzsm = (float*)(smem + SMEM_XZ_OFF);   // [3][33]

    const int ng = blockIdx.x;
    const int tid = threadIdx.x;
    const int wg = tid >> 5;
    const int lane = tid & 31;
    const int q = lane & 3;
    const int r4 = lane >> 2;
    const int R = 16 * wg + r4;

    // ---- One-time: weight slice -> fp16 B-fragments in SMEM ----
    for (int i = tid; i < 2 * KS16 * 32; i += NTHREADS) {
        int t = i & 31;
        int ks = (i >> 5) & 63;
        int p = i >> 11;                      // 0: gates g,i  1: gates f,o
        int col = ng * 8 + (t >> 2);
        int k0 = 16 * ks + 2 * (t & 3);
        const float* WA = p ? W_fh : W_gh;
        const float* WB = p ? W_oh : W_ih;
        uint4 v;
        v.x = packh2(WA[(size_t)k0 * HH + col],       WA[(size_t)(k0 + 1) * HH + col]);
        v.y = packh2(WA[(size_t)(k0 + 8) * HH + col], WA[(size_t)(k0 + 9) * HH + col]);
        v.z = packh2(WB[(size_t)k0 * HH + col],       WB[(size_t)(k0 + 1) * HH + col]);
        v.w = packh2(WB[(size_t)(k0 + 8) * HH + col], WB[(size_t)(k0 + 9) * HH + col]);
        Bf[i] = v;
    }

    // xz slice: xzsm[v][gate*8 + j] for this CTA's 8 cols
    for (int i = tid; i < VV * 32; i += NTHREADS) {
        int v = i >> 5;
        int lc = i & 31;
        xzsm[v * 33 + lc] = g_xz3[v * 4096 + (lc >> 3) * HH + ng * 8 + (lc & 7)];
    }

    // Producer write slot for this (ng, wg, lane): 8-byte half of a uint4.
    const int kp = ng >> 1;
    const int half = ng & 1;
    uint2* slot0 = (uint2*)((char*)&g_hpack[0][kp][wg][lane] + half * 8);
    uint2* slot1 = (uint2*)((char*)&g_hpack[1][kp][wg][lane] + half * 8);

    // h(0) = 0 for our fragment
    {
        uint2 z; z.x = 0u; z.y = 0u;
        *slot0 = z;
    }
    __syncthreads();               // SMEM init + zero stores complete
    publish_warp(ng, lane);        // flag -> 8 after all warps (level t=0)

    float c0 = 0.0f, c1 = 0.0f, c2 = 0.0f, c3 = 0.0f;

    for (int t = 0; t < TT; ++t) {
        const uint4* hp = &g_hpack[t & 1][0][wg][lane];   // stride per kp = 256 uint4
        const uint4* bf0 = Bf + lane;
        const uint4* bf1 = Bf + 2048 + lane;

        // Prefetch token indices for this step
        int vA = __ldg(&g_xidx[t * BB + R]);
        int vB = __ldg(&g_xidx[t * BB + R + 8]);

        float acc[4][4];
#pragma unroll
        for (int g = 0; g < 4; ++g)
#pragma unroll
            for (int e = 0; e < 4; ++e) acc[g][e] = 0.0f;

        const unsigned tgt = 8u * (unsigned)(t + 1);

        // 4 grouped waits in k-order (R4-proven pipelining): group g covers
        // producers [32g,32g+32) = kp [16g,16g+16).
#pragma unroll 1
        for (int grp = 0; grp < 4; ++grp) {
            wait_group(grp, tgt);
#pragma unroll 8
            for (int ks = 16 * grp; ks < 16 * grp + 16; ++ks) {
                uint4 A = ldcg4(hp + ks * 256);   // A01 = .x/.y, A23 = .z/.w
                uint4 B01 = bf0[ks * 32];
                uint4 B23 = bf1[ks * 32];
                mma_f16(acc[0], A.x, A.y, A.z, A.w, B01.x, B01.y);
                mma_f16(acc[1], A.x, A.y, A.z, A.w, B01.z, B01.w);
                mma_f16(acc[2], A.x, A.y, A.z, A.w, B23.x, B23.y);
                mma_f16(acc[3], A.x, A.y, A.z, A.w, B23.z, B23.w);
            }
        }

        // Gate math entirely in registers (C-fragment == gate-math element set)
        const float* xA = xzsm + vA * 33 + 2 * q;
        const float* xB = xzsm + vB * 33 + 2 * q;

        float h0 = lstm_elem(acc[0][0] + xA[0], acc[1][0] + xA[8],
                             acc[2][0] + xA[16], acc[3][0] + xA[24], c0);
        float h1 = lstm_elem(acc[0][1] + xA[1], acc[1][1] + xA[9],
                             acc[2][1] + xA[17], acc[3][1] + xA[25], c1);
        float h2 = lstm_elem(acc[0][2] + xB[0], acc[1][2] + xB[8],
                             acc[2][2] + xB[16], acc[3][2] + xB[24], c2);
        float h3 = lstm_elem(acc[0][3] + xB[1], acc[1][3] + xB[9],
                             acc[2][3] + xB[17], acc[3][3] + xB[25], c3);

        uint2 out;
        out.x = packh2(h0, h1);
        out.y = packh2(h2, h3);
        *((t & 1) ? slot0 : slot1) = out;     // h(t+1) -> buffer (t+1)&1

        // Per-warp arrival: no block-wide tail sync.
        publish_warp(ng, lane);
    }
}

// ---------------------------------------------------------------------------
// Final projection + log_softmax; decodes packed fragment layout (buf 0).
__global__ void k_final(const float* __restrict__ W_ph, const float* __restrict__ b_p,
                        float* __restrict__ out) {
    __shared__ float part[CC][128];
    __shared__ float lg[CC];
    __shared__ float red[2];
    int b = blockIdx.x;
    int tid = threadIdx.x;
    int wg = b >> 4;
    int rr = b & 7;
    int e1 = (b >> 3) & 1;

    float loc[CC];
#pragma unroll
    for (int c = 0; c < CC; ++c) loc[c] = 0.0f;
    for (int col = tid; col < HH; col += 128) {
        int ns2 = col >> 3;        // 8-col slice
        int kp = ns2 >> 1;
        int half = ns2 & 1;
        int q = (col & 7) >> 1;
        int e0 = col & 1;
        uint4 ent = g_hpack[0][kp][wg][rr * 4 + q];
        unsigned word;
        if (half) word = e1 ? ent.w : ent.z;
        else      word = e1 ? ent.y : ent.x;
        __half2 hh = *(__half2*)&word;
        float hv = e0 ? __high2float(hh) : __low2float(hh);
#pragma unroll
        for (int c = 0; c < CC; ++c) loc[c] += hv * W_ph[col * CC + c];
    }
#pragma unroll
    for (int c = 0; c < CC; ++c) part[c][tid] = loc[c];
    __syncthreads();
    if (tid < CC) {
        float s = 0.0f;
        for (int k = 0; k < 128; ++k) s += part[tid][k];
        lg[tid] = s + b_p[tid];
    }
    __syncthreads();
    if (tid == 0) {
        float m = -1e30f;
        for (int c = 0; c < CC; ++c) m = fmaxf(m, lg[c]);
        float s = 0.0f;
        for (int c = 0; c < CC; ++c) s += expf(lg[c] - m);
        red[0] = m;
        red[1] = logf(s);
    }
    __syncthreads();
    if (tid < CC) out[b * CC + tid] = lg[tid] - red[0] - red[1];
}

// ---------------------------------------------------------------------------
extern "C" void kernel_launch(void* const* d_in, const int* in_sizes, int n_in,
                              void* d_out, int out_size) {
    const void* x        = d_in[0];
    const float* emb     = (const float*)d_in[1];
    const float* W_gx    = (const float*)d_in[2];
    const float* W_ix    = (const float*)d_in[3];
    const float* W_fx    = (const float*)d_in[4];
    const float* W_ox    = (const float*)d_in[5];
    const float* W_gh    = (const float*)d_in[6];
    const float* W_ih    = (const float*)d_in[7];
    const float* W_fh    = (const float*)d_in[8];
    const float* W_oh    = (const float*)d_in[9];
    const float* b_g     = (const float*)d_in[10];
    const float* b_i     = (const float*)d_in[11];
    const float* b_f     = (const float*)d_in[12];
    const float* b_o     = (const float*)d_in[13];
    const float* W_ph    = (const float*)d_in[14];
    const float* b_p     = (const float*)d_in[15];
    float* out = (float*)d_out;

    cudaFuncSetAttribute(lstm_persistent, cudaFuncAttributeMaxDynamicSharedMemorySize,
                         SMEM_TOTAL);

    k_init<<<1, 128>>>();
    k_detect<<<1, 256>>>((const unsigned*)x);
    k_idx<<<BB, TT>>>(x);
    k_xz3<<<(VV * 4 * HH + 255) / 256, 256>>>(emb, W_gx, W_ix, W_fx, W_ox, b_g, b_i, b_f, b_o);
    lstm_persistent<<<GRID, NTHREADS, SMEM_TOTAL>>>(W_gh, W_ih, W_fh, W_oh);
    k_final<<<BB, 128>>>(W_ph, b_p, out);
}

// round 10
// speedup vs baseline: 1.2706x; 1.0004x over previous
#include <cuda_runtime.h>
#include <cuda_fp16.h>
#include <cstdint>

// Problem constants
#define BB 128      // batch
#define TT 256      // timesteps
#define DD 256      // embed dim
#define HH 1024     // hidden
#define CC 10       // classes
#define VV 3        // vocab
#define GRID 128    // CTA = (col-slice c = ng>>1) x (batch-half bh = ng&1)
#define NTHREADS 256
#define NWARP 8
#define KS16 64     // 1024 / 16

// SMEM: Bf uint4[2 cw][2][64][32] = 128KB weight fragments, then xzsm[3][68]
#define SMEM_BF_BYTES (2 * 2 * 64 * 32 * 16)
#define SMEM_XZ_OFF   SMEM_BF_BYTES
#define SMEM_TOTAL    (SMEM_XZ_OFF + 3 * 68 * 4)

// h in A-fragment order, fp16, PAIRED for LDG.128 (R8 layout, unchanged):
// g_hpack[buf][kp][rg_g][lane] = uint4 { 8-col slice 2kp (uint2), slice 2kp+1 }
// slice s covers h-cols [8s,8s+8). For (rg_g, lane): rows R=16*rg_g+lane/4, R+8;
// cols c0=8s+2*(lane%4), c0+1. CTA (c,bh) produces kp=c, rg_g in [4bh,4bh+4).
__device__ uint4 g_hpack[2][64][NWARP][32];
__device__ float g_xz3[VV * 4 * HH];   // x-side projection [v][gate*1024+j]
__device__ int   g_xidx[TT * BB];      // token index, time-major
__device__ int   g_x64;
// Per-CTA flags (R4-proven protocol). g_flag[ng] = s: CTA ng published h(s-1),
// hence finished reading h(s-2). Consumer of h(t) needs flag >= t+1 from the
// producers whose slots it reads (same batch-half; all col-slices).
// WAR across halves is safe: writer (c,bh) touches only rg_g in [4bh,4bh+4);
// other-half readers touch disjoint rg_g slots.
__device__ unsigned g_flag[GRID];

// ---------------------------------------------------------------------------
__device__ __forceinline__ unsigned packh2(float a, float b) {
    __half2 h = __floats2half2_rn(a, b);
    return *(unsigned*)&h;
}

// Default-cached vector load (L1-participating; dedup across the CTA's two
// col-warps). Stale-line safety = per-step gpu-scope fence (CCTL.IVALL).
__device__ __forceinline__ uint4 ldca4(const uint4* p) {
    uint4 r;
    asm volatile("ld.global.ca.v4.u32 {%0,%1,%2,%3},[%4];"
                 : "=r"(r.x), "=r"(r.y), "=r"(r.z), "=r"(r.w) : "l"(p));
    return r;
}

__device__ __forceinline__ void mma_f16(float* c, unsigned a0, unsigned a1,
                                        unsigned a2, unsigned a3,
                                        unsigned b0, unsigned b1) {
    asm volatile(
        "mma.sync.aligned.m16n8k16.row.col.f32.f16.f16.f32 "
        "{%0,%1,%2,%3}, {%4,%5,%6,%7}, {%8,%9}, {%0,%1,%2,%3};"
        : "+f"(c[0]), "+f"(c[1]), "+f"(c[2]), "+f"(c[3])
        : "r"(a0), "r"(a1), "r"(a2), "r"(a3), "r"(b0), "r"(b1));
}

__device__ __forceinline__ float tanha(float x) {
    float y;
    asm("tanh.approx.f32 %0,%1;" : "=f"(y) : "f"(x));
    return y;
}

__device__ __forceinline__ float sigmf(float x) {
    float e = __expf(-x);
    float r;
    asm("rcp.approx.f32 %0,%1;" : "=f"(r) : "f"(1.0f + e));
    return r;
}

__device__ __forceinline__ float lstm_elem(float zg, float zi, float zf, float zo, float& c) {
    float gg = tanha(zg);
    float ii = sigmf(zi);
    float ff = sigmf(zf);
    float oo = sigmf(zo);
    c = c * ff + gg * ii;
    return tanha(c) * oo;
}

// Warp-collective: wait until the 16 producers {2*(16g+j)+bh} have flag >= tgt.
// Lane L polls producer index j = L&15 (duplicated across half-warps).
__device__ __forceinline__ void wait_group(int g, int bh, unsigned tgt) {
    const unsigned* f = &g_flag[2 * (16 * g + (threadIdx.x & 15)) + bh];
    unsigned v;
    do {
        asm volatile("ld.acquire.gpu.global.u32 %0,[%1];" : "=r"(v) : "l"(f) : "memory");
    } while (__any_sync(0xffffffffu, v < tgt));
}

__device__ __forceinline__ void publish(int ng, unsigned val) {
    asm volatile("st.release.gpu.global.u32 [%0],%1;"
                 :: "l"(&g_flag[ng]), "r"(val) : "memory");
}

// ---------------------------------------------------------------------------
__global__ void k_init() {
    int tid = threadIdx.x;
    if (tid < GRID) g_flag[tid] = 0u;
}

// Detect x dtype without reading past an int32-sized allocation.
__global__ void k_detect(const unsigned* __restrict__ xw) {
    __shared__ int flag;
    if (threadIdx.x == 0) flag = 0;
    __syncthreads();
    for (int i = threadIdx.x; i < 2048; i += blockDim.x)
        if (xw[2 * i + 1] != 0u) flag = 1;
    __syncthreads();
    if (threadIdx.x == 0) g_x64 = (flag == 0) ? 1 : 0;
}

__global__ void k_idx(const void* __restrict__ x) {
    int b = blockIdx.x;
    int t = threadIdx.x;
    long long v;
    if (g_x64) v = ((const long long*)x)[(size_t)b * TT + t];
    else       v = ((const int*)x)[(size_t)b * TT + t];
    g_xidx[t * BB + b] = (int)v;
}

__global__ void k_xz3(const float* __restrict__ emb,
                      const float* __restrict__ W_gx, const float* __restrict__ W_ix,
                      const float* __restrict__ W_fx, const float* __restrict__ W_ox,
                      const float* __restrict__ b_g, const float* __restrict__ b_i,
                      const float* __restrict__ b_f, const float* __restrict__ b_o) {
    int gid = blockIdx.x * blockDim.x + threadIdx.x;
    if (gid >= VV * 4 * HH) return;
    int v = gid >> 12;
    int col = gid & 4095;
    int gate = col >> 10;
    int j = col & 1023;
    const float* W = (gate == 0) ? W_gx : (gate == 1) ? W_ix : (gate == 2) ? W_fx : W_ox;
    const float* bb = (gate == 0) ? b_g : (gate == 1) ? b_i : (gate == 2) ? b_f : b_o;
    float s = bb[j];
    const float* ev = emb + v * DD;
#pragma unroll 8
    for (int d = 0; d < DD; ++d) s += ev[d] * W[d * HH + j];
    g_xz3[gid] = s;
}

// ---------------------------------------------------------------------------
// Persistent recurrent kernel, 2-D tiled. CTA ng: col-slice c = ng>>1 owns
// h-cols [16c,16c+16); batch-half bh = ng&1 owns rows [64bh,64bh+64).
// Warp wg: rg = wg>>1 (rows 64bh+16rg..+16), cw = wg&1 (8-col half).
// The two cw warps of each rg issue IDENTICAL A loads -> L1 dedup halves the
// chip-wide L2 h-broadcast. Per-step __threadfence() (gpu scope, CCTL.IVALL)
// kills stale L1 lines from step t-2. Everything else is the R4 machinery.
__global__ void __launch_bounds__(NTHREADS, 1)
lstm_persistent(const float* __restrict__ W_gh, const float* __restrict__ W_ih,
                const float* __restrict__ W_fh, const float* __restrict__ W_oh) {
    extern __shared__ __align__(16) char smem[];
    uint4* Bf = (uint4*)smem;                     // [2 cw][2][64][32]
    float* xzsm = (float*)(smem + SMEM_XZ_OFF);   // [3][68]

    const int ng = blockIdx.x;
    const int c = ng >> 1;
    const int bh = ng & 1;
    const int tid = threadIdx.x;
    const int wg = tid >> 5;
    const int lane = tid & 31;
    const int rg = wg >> 1;        // 0..3
    const int cw = wg & 1;         // 0..1
    const int q = lane & 3;
    const int r4 = lane >> 2;
    const int rg_g = 4 * bh + rg;  // global row-group
    const int R = 16 * rg_g + r4;  // rows R, R+8

    // ---- One-time: weight fragments -> SMEM, per cw half (R4 layout x2) ----
    // For half cw: col = 16c + 8cw + (t>>2); p selects gates {g,i} vs {f,o}.
    for (int i = tid; i < 2 * 2 * KS16 * 32; i += NTHREADS) {
        int cwf = i >> 12;
        int e = i & 4095;
        int t = e & 31;
        int ks = (e >> 5) & 63;
        int p = e >> 11;
        int col = 16 * c + 8 * cwf + (t >> 2);
        int k0 = 16 * ks + 2 * (t & 3);
        const float* WA = p ? W_fh : W_gh;
        const float* WB = p ? W_oh : W_ih;
        uint4 v;
        v.x = packh2(WA[(size_t)k0 * HH + col],       WA[(size_t)(k0 + 1) * HH + col]);
        v.y = packh2(WA[(size_t)(k0 + 8) * HH + col], WA[(size_t)(k0 + 9) * HH + col]);
        v.z = packh2(WB[(size_t)k0 * HH + col],       WB[(size_t)(k0 + 1) * HH + col]);
        v.w = packh2(WB[(size_t)(k0 + 8) * HH + col], WB[(size_t)(k0 + 9) * HH + col]);
        Bf[i] = v;
    }

    // xz slice for the CTA's 16 h-cols: xzsm[v][gate*16 + local_col]
    for (int i = tid; i < VV * 64; i += NTHREADS) {
        int v = i >> 6;
        int lc = i & 63;
        int gate = lc >> 4;
        xzsm[v * 68 + lc] = g_xz3[v * 4096 + gate * 1024 + 16 * c + (lc & 15)];
    }

    // Producer write slot: uint2 half (cw) of g_hpack[buf][c][rg_g][lane]
    uint2* slot0 = (uint2*)((char*)&g_hpack[0][c][rg_g][lane] + cw * 8);
    uint2* slot1 = (uint2*)((char*)&g_hpack[1][c][rg_g][lane] + cw * 8);

    // h(0) = 0
    {
        uint2 z; z.x = 0u; z.y = 0u;
        *slot0 = z;
    }
    __syncthreads();
    if (tid == 0) publish(ng, 1u);

    float c0 = 0.0f, c1 = 0.0f, c2 = 0.0f, c3 = 0.0f;
    const uint4* bfw = Bf + cw * 4096;

    for (int t = 0; t < TT; ++t) {
        // gpu-scope fence: flush L1D (stale h lines from step t-2) before any
        // cached A load this step. Each warp fences itself before its loads.
        __threadfence();

        const uint4* hp = &g_hpack[t & 1][0][rg_g][lane];   // kp stride = 256 uint4
        const uint4* bf0 = bfw + lane;
        const uint4* bf1 = bfw + 2048 + lane;

        // Prefetch token indices for this thread's two rows
        int vA = __ldg(&g_xidx[t * BB + R]);
        int vB = __ldg(&g_xidx[t * BB + R + 8]);

        float acc[4][4];
#pragma unroll
        for (int g = 0; g < 4; ++g)
#pragma unroll
            for (int e = 0; e < 4; ++e) acc[g][e] = 0.0f;

        const unsigned tgt = (unsigned)(t + 1);

        // 4 grouped waits in k-order (R4-proven pipelining): group g needs
        // producers c' in [16g,16g+16) of our batch half (kp = c' = ks).
#pragma unroll 1
        for (int grp = 0; grp < 4; ++grp) {
            wait_group(grp, bh, tgt);
#pragma unroll 8
            for (int ks = 16 * grp; ks < 16 * grp + 16; ++ks) {
                uint4 A = ldca4(hp + ks * 256);   // A01 = .x/.y, A23 = .z/.w
                uint4 B01 = bf0[ks * 32];
                uint4 B23 = bf1[ks * 32];
                mma_f16(acc[0], A.x, A.y, A.z, A.w, B01.x, B01.y);
                mma_f16(acc[1], A.x, A.y, A.z, A.w, B01.z, B01.w);
                mma_f16(acc[2], A.x, A.y, A.z, A.w, B23.x, B23.y);
                mma_f16(acc[3], A.x, A.y, A.z, A.w, B23.z, B23.w);
            }
        }

        // Gate math in registers. This warp's z-cols: gate*16 + 8cw + 2q (+1).
        const float* xA = xzsm + vA * 68 + 8 * cw + 2 * q;
        const float* xB = xzsm + vB * 68 + 8 * cw + 2 * q;

        float h0 = lstm_elem(acc[0][0] + xA[0], acc[1][0] + xA[16],
                             acc[2][0] + xA[32], acc[3][0] + xA[48], c0);
        float h1 = lstm_elem(acc[0][1] + xA[1], acc[1][1] + xA[17],
                             acc[2][1] + xA[33], acc[3][1] + xA[49], c1);
        float h2 = lstm_elem(acc[0][2] + xB[0], acc[1][2] + xB[16],
                             acc[2][2] + xB[32], acc[3][2] + xB[48], c2);
        float h3 = lstm_elem(acc[0][3] + xB[1], acc[1][3] + xB[17],
                             acc[2][3] + xB[33], acc[3][3] + xB[49], c3);

        uint2 out;
        out.x = packh2(h0, h1);   // (R,   2q / 2q+1)
        out.y = packh2(h2, h3);   // (R+8, 2q / 2q+1)
        *((t & 1) ? slot0 : slot1) = out;     // h(t+1) -> buffer (t+1)&1

        // Publish h(t+1): CTA stores ordered before the release store.
        __syncthreads();
        if (tid == 0) publish(ng, (unsigned)(t + 2));
    }
}

// ---------------------------------------------------------------------------
// Final projection + log_softmax; decodes packed fragment layout (buf 0).
__global__ void k_final(const float* __restrict__ W_ph, const float* __restrict__ b_p,
                        float* __restrict__ out) {
    __shared__ float part[CC][128];
    __shared__ float lg[CC];
    __shared__ float red[2];
    int b = blockIdx.x;
    int tid = threadIdx.x;
    int wg = b >> 4;
    int rr = b & 7;
    int e1 = (b >> 3) & 1;

    float loc[CC];
#pragma unroll
    for (int c = 0; c < CC; ++c) loc[c] = 0.0f;
    for (int col = tid; col < HH; col += 128) {
        int ns2 = col >> 3;        // 8-col slice
        int kp = ns2 >> 1;
        int half = ns2 & 1;
        int q = (col & 7) >> 1;
        int e0 = col & 1;
        uint4 ent = g_hpack[0][kp][wg][rr * 4 + q];
        unsigned word;
        if (half) word = e1 ? ent.w : ent.z;
        else      word = e1 ? ent.y : ent.x;
        __half2 hh = *(__half2*)&word;
        float hv = e0 ? __high2float(hh) : __low2float(hh);
#pragma unroll
        for (int c = 0; c < CC; ++c) loc[c] += hv * W_ph[col * CC + c];
    }
#pragma unroll
    for (int c = 0; c < CC; ++c) part[c][tid] = loc[c];
    __syncthreads();
    if (tid < CC) {
        float s = 0.0f;
        for (int k = 0; k < 128; ++k) s += part[tid][k];
        lg[tid] = s + b_p[tid];
    }
    __syncthreads();
    if (tid == 0) {
        float m = -1e30f;
        for (int c = 0; c < CC; ++c) m = fmaxf(m, lg[c]);
        float s = 0.0f;
        for (int c = 0; c < CC; ++c) s += expf(lg[c] - m);
        red[0] = m;
        red[1] = logf(s);
    }
    __syncthreads();
    if (tid < CC) out[b * CC + tid] = lg[tid] - red[0] - red[1];
}

// ---------------------------------------------------------------------------
extern "C" void kernel_launch(void* const* d_in, const int* in_sizes, int n_in,
                              void* d_out, int out_size) {
    const void* x        = d_in[0];
    const float* emb     = (const float*)d_in[1];
    const float* W_gx    = (const float*)d_in[2];
    const float* W_ix    = (const float*)d_in[3];
    const float* W_fx    = (const float*)d_in[4];
    const float* W_ox    = (const float*)d_in[5];
    const float* W_gh    = (const float*)d_in[6];
    const float* W_ih    = (const float*)d_in[7];
    const float* W_fh    = (const float*)d_in[8];
    const float* W_oh    = (const float*)d_in[9];
    const float* b_g     = (const float*)d_in[10];
    const float* b_i     = (const float*)d_in[11];
    const float* b_f     = (const float*)d_in[12];
    const float* b_o     = (const float*)d_in[13];
    const float* W_ph    = (const float*)d_in[14];
    const float* b_p     = (const float*)d_in[15];
    float* out = (float*)d_out;

    cudaFuncSetAttribute(lstm_persistent, cudaFuncAttributeMaxDynamicSharedMemorySize,
                         SMEM_TOTAL);

    k_init<<<1, 128>>>();
    k_detect<<<1, 256>>>((const unsigned*)x);
    k_idx<<<BB, TT>>>(x);
    k_xz3<<<(VV * 4 * HH + 255) / 256, 256>>>(emb, W_gx, W_ix, W_fx, W_ox, b_g, b_i, b_f, b_o);
    lstm_persistent<<<GRID, NTHREADS, SMEM_TOTAL>>>(W_gh, W_ih, W_fh, W_oh);
    k_final<<<BB, 128>>>(W_ph, b_p, out);
}